// round 1
// baseline (speedup 1.0000x reference)
#include <cuda_runtime.h>
#include <cstdint>

// ---------------- problem constants ----------------
#define NB   1024
#define H1   28
#define W1   28
#define HW1  784      // 28*28
#define H2   14
#define W2c  14
#define HW2  196      // 14*14
#define C1   32       // channels after deform1
#define C2   64       // channels after deform2
#define KK   9
#define K2D  288      // 32*9, K of deform2 GEMM
#define FCK  12544    // 64*196
#define FCN  128
#define SPLITK 16
#define KCHUNK 784    // 12544/16

// ---------------- device scratch (no allocations allowed) ----------------
__device__ float g_off1[(size_t)NB * 18 * HW1];          // 57.8 MB
__device__ float g_h1  [(size_t)NB * C1 * HW2];          // 25.7 MB
__device__ float g_off2[(size_t)NB * 18 * HW2];          // 14.4 MB
__device__ float g_w2r [C2 * K2D];                       // rearranged w2: [o][kt*32+c]
__device__ float g_samp[(size_t)NB * HW2 * K2D];         // 231 MB im2col
__device__ float g_h2  [(size_t)NB * FCK];               // 51.4 MB (flattened, c*196+hw)
__device__ float g_a1p [(size_t)SPLITK * NB * FCN];      // 8 MB partials
__device__ float g_a1  [(size_t)NB * FCN];               // fc1 activations

// ---------------- helpers ----------------
__device__ __forceinline__ float bilin(const float* __restrict__ img, int H, int W,
                                       float py, float px) {
    float y0f = floorf(py), x0f = floorf(px);
    int y0 = (int)y0f, x0 = (int)x0f;
    float wy1 = py - y0f, wx1 = px - x0f;
    float wy0 = 1.f - wy1, wx0 = 1.f - wx1;
    bool yv0 = (y0 >= 0) && (y0 < H);
    bool yv1 = (y0 >= -1) && (y0 < H - 1);
    bool xv0 = (x0 >= 0) && (x0 < W);
    bool xv1 = (x0 >= -1) && (x0 < W - 1);
    int yc0 = min(max(y0, 0), H - 1),   yc1 = min(max(y0 + 1, 0), H - 1);
    int xc0 = min(max(x0, 0), W - 1),   xc1 = min(max(x0 + 1, 0), W - 1);
    float v = 0.f;
    v += (yv0 && xv0) ? wy0 * wx0 * img[yc0 * W + xc0] : 0.f;
    v += (yv0 && xv1) ? wy0 * wx1 * img[yc0 * W + xc1] : 0.f;
    v += (yv1 && xv0) ? wy1 * wx0 * img[yc1 * W + xc0] : 0.f;
    v += (yv1 && xv1) ? wy1 * wx1 * img[yc1 * W + xc1] : 0.f;
    return v;
}

// ---------------- K0: rearrange w2 (O,C,3,3) -> (O, kt*32+c) ----------------
__global__ void k_prep(const float* __restrict__ w2) {
    for (int i = threadIdx.x; i < C2 * K2D; i += blockDim.x) {
        int o = i / K2D, r = i % K2D;
        int kt = r / 32, c = r % 32;
        g_w2r[i] = w2[o * K2D + c * 9 + kt];
    }
}

// ---------------- K1: offset conv1 (1->18 ch, 28x28) ----------------
__global__ void __launch_bounds__(256) k_offset1(const float* __restrict__ x,
                                                 const float* __restrict__ ow1,
                                                 const float* __restrict__ ob1) {
    __shared__ float sw[162];
    __shared__ float sb[18];
    if (threadIdx.x < 162) sw[threadIdx.x] = ow1[threadIdx.x];
    if (threadIdx.x < 18)  sb[threadIdx.x] = ob1[threadIdx.x];
    __syncthreads();
    int t = blockIdx.x * blockDim.x + threadIdx.x;
    if (t >= NB * HW1) return;
    int b = t / HW1, hw = t % HW1, y = hw / W1, xx = hw % W1;
    const float* xb = &x[(size_t)b * HW1];
    float p[9];
#pragma unroll
    for (int ky = 0; ky < 3; ky++)
#pragma unroll
        for (int kx = 0; kx < 3; kx++) {
            int y2 = y + ky - 1, x2 = xx + kx - 1;
            bool ok = (y2 >= 0) && (y2 < H1) && (x2 >= 0) && (x2 < W1);
            p[ky * 3 + kx] = ok ? xb[y2 * W1 + x2] : 0.f;
        }
#pragma unroll
    for (int o = 0; o < 18; o++) {
        float s = sb[o];
#pragma unroll
        for (int k = 0; k < 9; k++) s += sw[o * 9 + k] * p[k];
        g_off1[((size_t)b * 18 + o) * HW1 + hw] = s;
    }
}

// ---------------- K2: deform conv1 + relu + 2x2 avg-pool ----------------
__global__ void __launch_bounds__(256) k_deform1(const float* __restrict__ x,
                                                 const float* __restrict__ w1,
                                                 const float* __restrict__ b1) {
    int b = blockIdx.x;
    __shared__ float sx[HW1];
    __shared__ float sw[C1 * 9];
    __shared__ float sb[C1];
    for (int i = threadIdx.x; i < HW1; i += blockDim.x) sx[i] = x[(size_t)b * HW1 + i];
    for (int i = threadIdx.x; i < C1 * 9; i += blockDim.x) sw[i] = w1[i];
    if (threadIdx.x < C1) sb[threadIdx.x] = b1[threadIdx.x];
    __syncthreads();
    int t = threadIdx.x;
    if (t >= HW2) return;
    int ph = t / W2c, pw = t % W2c;
    float acc[C1];
#pragma unroll
    for (int o = 0; o < C1; o++) acc[o] = 0.f;
#pragma unroll
    for (int sy = 0; sy < 2; sy++)
#pragma unroll
        for (int sxi = 0; sxi < 2; sxi++) {
            int y = ph * 2 + sy, w = pw * 2 + sxi;
            float s[9];
#pragma unroll
            for (int k = 0; k < 9; k++) {
                int ky = k / 3, kx = k % 3;
                float dy = g_off1[((size_t)b * 18 + 2 * k)     * HW1 + y * W1 + w];
                float dx = g_off1[((size_t)b * 18 + 2 * k + 1) * HW1 + y * W1 + w];
                float py = dy + (float)(y - 1 + ky);
                float px = dx + (float)(w - 1 + kx);
                s[k] = bilin(sx, H1, W1, py, px);
            }
#pragma unroll
            for (int o = 0; o < C1; o++) {
                float v = sb[o];
#pragma unroll
                for (int k = 0; k < 9; k++) v += sw[o * 9 + k] * s[k];
                acc[o] += fmaxf(v, 0.f);
            }
        }
#pragma unroll
    for (int o = 0; o < C1; o++)
        g_h1[((size_t)b * C1 + o) * HW2 + t] = acc[o] * 0.25f;
}

// ---------------- K3: offset conv2 (32->18 ch, 14x14), 3x4 micro-tile ----------------
__global__ void __launch_bounds__(320) k_offset2(const float* __restrict__ ow2,
                                                 const float* __restrict__ ob2) {
    int b = blockIdx.x;
    __shared__ float sh[C1 * 197];       // padded channel stride (bank-friendly)
    __shared__ float sw[18 * K2D];
    for (int i = threadIdx.x; i < C1 * HW2; i += blockDim.x) {
        int c = i / HW2, hw = i % HW2;
        sh[c * 197 + hw] = g_h1[(size_t)b * (C1 * HW2) + i];
    }
    for (int i = threadIdx.x; i < 18 * K2D; i += blockDim.x) sw[i] = ow2[i];
    __syncthreads();
    int t = threadIdx.x;
    if (t >= 294) return;
    int og = t / 49, pg = t % 49;
    int o0 = og * 3;
    float acc[3][4];
#pragma unroll
    for (int q = 0; q < 3; q++)
#pragma unroll
        for (int p = 0; p < 4; p++) acc[q][p] = ob2[o0 + q];
    int ys[4], xs[4];
#pragma unroll
    for (int p = 0; p < 4; p++) { int hw = pg * 4 + p; ys[p] = hw / W2c; xs[p] = hw % W2c; }
#pragma unroll
    for (int kt = 0; kt < 9; kt++) {
        int ky = kt / 3, kx = kt % 3;
        int addr[4];
#pragma unroll
        for (int p = 0; p < 4; p++) {
            int y2 = ys[p] + ky - 1, x2 = xs[p] + kx - 1;
            bool ok = (y2 >= 0) && (y2 < H2) && (x2 >= 0) && (x2 < W2c);
            addr[p] = ok ? y2 * W2c + x2 : -1;
        }
        for (int c = 0; c < C1; c++) {
            float w0 = sw[(o0 + 0) * K2D + c * 9 + kt];
            float w1v = sw[(o0 + 1) * K2D + c * 9 + kt];
            float w2v = sw[(o0 + 2) * K2D + c * 9 + kt];
            const float* im = &sh[c * 197];
#pragma unroll
            for (int p = 0; p < 4; p++) {
                float v = (addr[p] >= 0) ? im[addr[p]] : 0.f;
                acc[0][p] += w0 * v;
                acc[1][p] += w1v * v;
                acc[2][p] += w2v * v;
            }
        }
    }
#pragma unroll
    for (int q = 0; q < 3; q++)
#pragma unroll
        for (int p = 0; p < 4; p++)
            g_off2[((size_t)b * 18 + o0 + q) * HW2 + pg * 4 + p] = acc[q][p];
}

// ---------------- K4: bilinear sampling -> im2col (lane = channel, coalesced) ----------------
__global__ void __launch_bounds__(256) k_samp() {
    int b = blockIdx.x;
    __shared__ float sh[C1 * 197];
    for (int i = threadIdx.x; i < C1 * HW2; i += blockDim.x) {
        int c = i / HW2, hw = i % HW2;
        sh[c * 197 + hw] = g_h1[(size_t)b * (C1 * HW2) + i];
    }
    __syncthreads();
    int warp = threadIdx.x >> 5, lane = threadIdx.x & 31;
    for (int hw = warp; hw < HW2; hw += 8) {
        int y = hw / W2c, xx = hw % W2c;
#pragma unroll
        for (int k = 0; k < 9; k++) {
            int ky = k / 3, kx = k % 3;
            float dy = g_off2[((size_t)b * 18 + 2 * k)     * HW2 + hw];
            float dx = g_off2[((size_t)b * 18 + 2 * k + 1) * HW2 + hw];
            float py = dy + (float)(y - 1 + ky);
            float px = dx + (float)(xx - 1 + kx);
            const float* im = &sh[lane * 197];
            float v = bilin(im, H2, W2c, py, px);
            g_samp[((size_t)(b * HW2 + hw)) * K2D + k * 32 + lane] = v;
        }
    }
}

// ---------------- GEMM: BM=128, BN=64, BK=16, 256 thr, 8x4 micro-tile ----------------
// MODE 0: C(200704x64) = g_samp * g_w2r^T, epilogue +bias, relu, scatter to g_h2
// MODE 1: partial C for fc1: g_a1p[z] = g_h2_chunk * fw1_chunk^T
template <int MODE>
__global__ void __launch_bounds__(256) k_gemm(const float* __restrict__ Bwp,
                                              const float* __restrict__ bias,
                                              int lda, int k_chunk, int k_iters) {
    const float* __restrict__ A  = (MODE == 0) ? g_samp : g_h2;
    const float* __restrict__ Bw = (MODE == 0) ? g_w2r  : Bwp;
    __shared__ float As[16][128];
    __shared__ float Bs[16][64];
    int m0 = blockIdx.x * 128;
    int n0 = blockIdx.y * 64;
    int kbase = blockIdx.z * k_chunk;
    int tid = threadIdx.x;
    int ty = tid / 16, tx = tid % 16;
    float acc[8][4];
#pragma unroll
    for (int i = 0; i < 8; i++)
#pragma unroll
        for (int j = 0; j < 4; j++) acc[i][j] = 0.f;

    for (int t = 0; t < k_iters; t++) {
        int k0 = kbase + t * 16;
#pragma unroll
        for (int i = 0; i < 2; i++) {
            int e = tid + i * 256;
            int m = e >> 2, kq = e & 3;
            float4 v = *(const float4*)&A[(size_t)(m0 + m) * lda + k0 + kq * 4];
            As[kq * 4 + 0][m] = v.x; As[kq * 4 + 1][m] = v.y;
            As[kq * 4 + 2][m] = v.z; As[kq * 4 + 3][m] = v.w;
        }
        {
            int n = tid >> 2, kq = tid & 3;
            float4 v = *(const float4*)&Bw[(size_t)(n0 + n) * lda + k0 + kq * 4];
            Bs[kq * 4 + 0][n] = v.x; Bs[kq * 4 + 1][n] = v.y;
            Bs[kq * 4 + 2][n] = v.z; Bs[kq * 4 + 3][n] = v.w;
        }
        __syncthreads();
#pragma unroll
        for (int k = 0; k < 16; k++) {
            float4 a0 = *(const float4*)&As[k][ty * 8];
            float4 a1 = *(const float4*)&As[k][ty * 8 + 4];
            float4 b0 = *(const float4*)&Bs[k][tx * 4];
            float ar[8] = {a0.x, a0.y, a0.z, a0.w, a1.x, a1.y, a1.z, a1.w};
            float br[4] = {b0.x, b0.y, b0.z, b0.w};
#pragma unroll
            for (int i = 0; i < 8; i++)
#pragma unroll
                for (int j = 0; j < 4; j++) acc[i][j] += ar[i] * br[j];
        }
        __syncthreads();
    }

#pragma unroll
    for (int i = 0; i < 8; i++) {
        int m = m0 + ty * 8 + i;
#pragma unroll
        for (int j = 0; j < 4; j++) {
            int n = n0 + tx * 4 + j;
            float v = acc[i][j];
            if (MODE == 0) {
                v = fmaxf(v + bias[n], 0.f);
                int b = m / HW2, hw = m % HW2;
                g_h2[(size_t)b * FCK + n * HW2 + hw] = v;   // flatten c*196+hw
            } else {
                g_a1p[((size_t)blockIdx.z * NB + m) * FCN + n] = v;
            }
        }
    }
}

// ---------------- K6b: reduce split-K partials + bias + relu ----------------
__global__ void __launch_bounds__(256) k_fc1fin(const float* __restrict__ fb1) {
    int t = blockIdx.x * blockDim.x + threadIdx.x;   // 1024*128
    if (t >= NB * FCN) return;
    int n = t & (FCN - 1);
    float s = fb1[n];
#pragma unroll
    for (int z = 0; z < SPLITK; z++) s += g_a1p[(size_t)z * NB * FCN + t];
    g_a1[t] = fmaxf(s, 0.f);
}

// ---------------- K7: fc2 ----------------
__global__ void __launch_bounds__(256) k_fc2(const float* __restrict__ fw2,
                                             const float* __restrict__ fb2,
                                             float* __restrict__ out) {
    int t = blockIdx.x * blockDim.x + threadIdx.x;   // 1024*10
    if (t >= NB * 10) return;
    int b = t / 10, o = t % 10;
    float s = fb2[o];
    const float* a = &g_a1[(size_t)b * FCN];
    const float* w = &fw2[(size_t)o * FCN];
#pragma unroll 16
    for (int j = 0; j < FCN; j++) s += a[j] * w[j];
    out[t] = s;
}

// ---------------- launch ----------------
extern "C" void kernel_launch(void* const* d_in, const int* in_sizes, int n_in,
                              void* d_out, int out_size) {
    const float* x   = (const float*)d_in[0];
    const float* ow1 = (const float*)d_in[1];
    const float* ob1 = (const float*)d_in[2];
    const float* w1  = (const float*)d_in[3];
    const float* b1  = (const float*)d_in[4];
    const float* ow2 = (const float*)d_in[5];
    const float* ob2 = (const float*)d_in[6];
    const float* w2  = (const float*)d_in[7];
    const float* b2  = (const float*)d_in[8];
    const float* fw1 = (const float*)d_in[9];
    const float* fb1 = (const float*)d_in[10];
    const float* fw2 = (const float*)d_in[11];
    const float* fb2 = (const float*)d_in[12];
    float* out = (float*)d_out;
    (void)in_sizes; (void)n_in; (void)out_size;

    k_prep<<<1, 256>>>(w2);
    k_offset1<<<(NB * HW1) / 256, 256>>>(x, ow1, ob1);
    k_deform1<<<NB, 256>>>(x, w1, b1);
    k_offset2<<<NB, 320>>>(ow2, ob2);
    k_samp<<<NB, 256>>>();
    // deform2 GEMM: M=200704 (1568 blocks of 128), N=64, K=288 (18 tiles)
    k_gemm<0><<<dim3(1568, 1, 1), 256>>>(nullptr, b2, K2D, 0, 18);
    // fc1 GEMM split-K: M=1024 (8), N=128 (2), 16 K-splits of 784 (49 tiles)
    k_gemm<1><<<dim3(8, 2, SPLITK), 256>>>(fw1, nullptr, FCK, KCHUNK, KCHUNK / 16);
    k_fc1fin<<<(NB * FCN) / 256, 256>>>(fb1);
    k_fc2<<<(NB * 10 + 255) / 256, 256>>>(fw2, fb2, out);
}

// round 2
// speedup vs baseline: 1.0873x; 1.0873x over previous
#include <cuda_runtime.h>
#include <cstdint>

// ---------------- problem constants ----------------
#define NB   1024
#define H1   28
#define W1   28
#define HW1  784
#define H2   14
#define W2c  14
#define HW2  196
#define C1   32
#define C2   64
#define K2D  288      // 32*9
#define FCK  12544    // 64*196
#define FCN  128
#define SPLITK 16
#define KCHUNK 784

// ---------------- device scratch ----------------
__device__ float g_h1  [(size_t)NB * C1 * HW2];
__device__ float g_off2[(size_t)NB * 18 * HW2];
__device__ float g_w2r [C2 * K2D];                       // [o][kt*32+c]
__device__ float g_fw1r[(size_t)FCN * FCK];              // [n][hw*64+c]
__device__ float g_samp[(size_t)NB * HW2 * K2D];         // [(b*196+hw)][kt*32+c]
__device__ float g_h2  [(size_t)NB * HW2 * C2];          // [(b*196+hw)][c]  (m-major!)
__device__ float g_a1p [(size_t)SPLITK * NB * FCN];
__device__ float g_a1  [(size_t)NB * FCN];

// ---------------- helpers ----------------
__device__ __forceinline__ float bilin(const float* __restrict__ img, int H, int W,
                                       float py, float px) {
    float y0f = floorf(py), x0f = floorf(px);
    int y0 = (int)y0f, x0 = (int)x0f;
    float wy1 = py - y0f, wx1 = px - x0f;
    float wy0 = 1.f - wy1, wx0 = 1.f - wx1;
    bool yv0 = (y0 >= 0) && (y0 < H);
    bool yv1 = (y0 >= -1) && (y0 < H - 1);
    bool xv0 = (x0 >= 0) && (x0 < W);
    bool xv1 = (x0 >= -1) && (x0 < W - 1);
    int yc0 = min(max(y0, 0), H - 1),   yc1 = min(max(y0 + 1, 0), H - 1);
    int xc0 = min(max(x0, 0), W - 1),   xc1 = min(max(x0 + 1, 0), W - 1);
    float v = 0.f;
    v += (yv0 && xv0) ? wy0 * wx0 * img[yc0 * W + xc0] : 0.f;
    v += (yv0 && xv1) ? wy0 * wx1 * img[yc0 * W + xc1] : 0.f;
    v += (yv1 && xv0) ? wy1 * wx0 * img[yc1 * W + xc0] : 0.f;
    v += (yv1 && xv1) ? wy1 * wx1 * img[yc1 * W + xc1] : 0.f;
    return v;
}

// ---------------- K0: weight rearranges ----------------
__global__ void k_prep(const float* __restrict__ w2, const float* __restrict__ fw1) {
    int t = blockIdx.x * blockDim.x + threadIdx.x;
    if (t < C2 * K2D) {
        int o = t / K2D, r = t % K2D, kt = r / 32, c = r % 32;
        g_w2r[t] = w2[o * K2D + c * 9 + kt];
    }
    int stride = gridDim.x * blockDim.x;
    for (int i = t; i < FCN * FCK; i += stride) {
        int n = i / FCK, r = i % FCK, hw = r / 64, c = r % 64;
        g_fw1r[i] = fw1[(size_t)n * FCK + c * HW2 + hw];
    }
}

// ---------------- K1: fused offset-conv1 + deform-conv1 + relu + pool ----------------
__global__ void __launch_bounds__(224) k_deform1(const float* __restrict__ x,
                                                 const float* __restrict__ ow1,
                                                 const float* __restrict__ ob1,
                                                 const float* __restrict__ w1,
                                                 const float* __restrict__ b1) {
    int b = blockIdx.x;
    __shared__ float sx[HW1];
    __shared__ float sow[162];
    __shared__ float sob[18];
    __shared__ float swt[C1 * 9];
    __shared__ float sb[C1];
    for (int i = threadIdx.x; i < HW1; i += 224) sx[i] = x[(size_t)b * HW1 + i];
    if (threadIdx.x < 162) sow[threadIdx.x] = ow1[threadIdx.x];
    if (threadIdx.x < 18)  sob[threadIdx.x] = ob1[threadIdx.x];
    for (int i = threadIdx.x; i < C1 * 9; i += 224) swt[i] = w1[i];
    if (threadIdx.x < C1) sb[threadIdx.x] = b1[threadIdx.x];
    __syncthreads();
    int t = threadIdx.x;
    if (t >= HW2) return;
    int ph = t / W2c, pw = t % W2c;
    float acc[C1];
#pragma unroll
    for (int o = 0; o < C1; o++) acc[o] = 0.f;
#pragma unroll 1
    for (int s4 = 0; s4 < 4; s4++) {
        int y = ph * 2 + (s4 >> 1), w = pw * 2 + (s4 & 1);
        // neighborhood for offset conv
        float p[9];
#pragma unroll
        for (int ky = 0; ky < 3; ky++)
#pragma unroll
            for (int kx = 0; kx < 3; kx++) {
                int y2 = y + ky - 1, x2 = w + kx - 1;
                bool ok = (y2 >= 0) && (y2 < H1) && (x2 >= 0) && (x2 < W1);
                p[ky * 3 + kx] = ok ? sx[y2 * W1 + x2] : 0.f;
            }
        float s[9];
#pragma unroll
        for (int k = 0; k < 9; k++) {
            float dy = sob[2 * k], dx = sob[2 * k + 1];
#pragma unroll
            for (int j = 0; j < 9; j++) {
                dy += sow[(2 * k) * 9 + j] * p[j];
                dx += sow[(2 * k + 1) * 9 + j] * p[j];
            }
            int ky = k / 3, kx = k % 3;
            s[k] = bilin(sx, H1, W1, dy + (float)(y - 1 + ky), dx + (float)(w - 1 + kx));
        }
#pragma unroll
        for (int o = 0; o < C1; o++) {
            float v = sb[o];
#pragma unroll
            for (int k = 0; k < 9; k++) v += swt[o * 9 + k] * s[k];
            acc[o] += fmaxf(v, 0.f);
        }
    }
#pragma unroll
    for (int o = 0; o < C1; o++)
        g_h1[((size_t)b * C1 + o) * HW2 + t] = acc[o] * 0.25f;
}

// ---------------- K2: offset conv2, padded smem + register neighborhood ----------------
// thread = (og 0..5 -> 3 outputs, pg 0..27 -> 7 pixels of half-row)
__global__ void __launch_bounds__(192) k_offset2(const float* __restrict__ ow2,
                                                 const float* __restrict__ ob2) {
    int b = blockIdx.x;
    __shared__ float sh[16 * 256];     // 16 channels, 16x16 zero-padded tiles
    __shared__ float sw[18 * 144];     // 18 outputs x (16 ch * 9 taps)
    int t = threadIdx.x;
    bool act = t < 168;
    int og = t / 28, pg = t % 28;
    int y = pg >> 1, x0 = (pg & 1) * 7;
    int o0 = og * 3;
    float acc[3][7];
    if (act) {
#pragma unroll
        for (int q = 0; q < 3; q++) {
            float bv = ob2[o0 + q];
#pragma unroll
            for (int p = 0; p < 7; p++) acc[q][p] = bv;
        }
    }
#pragma unroll 1
    for (int half = 0; half < 2; half++) {
        if (half) __syncthreads();
        // zero borders (disjoint from interior fill -> no intermediate barrier)
        for (int i = t; i < 16 * 60; i += 192) {
            int c = i / 60, e = i % 60;
            int py, px;
            if (e < 16)      { py = 0;  px = e; }
            else if (e < 32) { py = 15; px = e - 16; }
            else { int e2 = e - 32; py = 1 + (e2 >> 1); px = (e2 & 1) * 15; }
            sh[c * 256 + py * 16 + px] = 0.f;
        }
        // interior fill
        for (int i = t; i < 16 * HW2; i += 192) {
            int c = i / HW2, hw = i % HW2, yy = hw / W2c, xx = hw % W2c;
            sh[c * 256 + (yy + 1) * 16 + (xx + 1)] =
                g_h1[(size_t)b * (C1 * HW2) + (half * 16 + c) * HW2 + hw];
        }
        // weights for this half
        for (int i = t; i < 18 * 144; i += 192) {
            int o = i / 144, r = i % 144, cl = r / 9, kt = r % 9;
            sw[i] = ow2[o * K2D + (half * 16 + cl) * 9 + kt];
        }
        __syncthreads();
        if (act) {
#pragma unroll 1
            for (int c = 0; c < 16; c++) {
                const float* base = &sh[c * 256 + y * 16 + x0];
                float nb[27];
#pragma unroll
                for (int dy = 0; dy < 3; dy++)
#pragma unroll
                    for (int dx = 0; dx < 9; dx++)
                        nb[dy * 9 + dx] = base[dy * 16 + dx];
#pragma unroll
                for (int kt = 0; kt < 9; kt++) {
                    int ky = kt / 3, kx = kt % 3;
                    float w0 = sw[(o0 + 0) * 144 + c * 9 + kt];
                    float w1v = sw[(o0 + 1) * 144 + c * 9 + kt];
                    float w2v = sw[(o0 + 2) * 144 + c * 9 + kt];
#pragma unroll
                    for (int p = 0; p < 7; p++) {
                        float v = nb[ky * 9 + kx + p];
                        acc[0][p] += w0 * v;
                        acc[1][p] += w1v * v;
                        acc[2][p] += w2v * v;
                    }
                }
            }
        }
    }
    if (act) {
#pragma unroll
        for (int q = 0; q < 3; q++)
#pragma unroll
            for (int p = 0; p < 7; p++)
                g_off2[((size_t)b * 18 + o0 + q) * HW2 + y * W2c + x0 + p] = acc[q][p];
    }
}

// ---------------- K3: bilinear sampling -> im2col ----------------
__global__ void __launch_bounds__(256) k_samp() {
    int b = blockIdx.x;
    __shared__ float sh[C1 * 197];
    for (int i = threadIdx.x; i < C1 * HW2; i += blockDim.x) {
        int c = i / HW2, hw = i % HW2;
        sh[c * 197 + hw] = g_h1[(size_t)b * (C1 * HW2) + i];
    }
    __syncthreads();
    int warp = threadIdx.x >> 5, lane = threadIdx.x & 31;
    for (int hw = warp; hw < HW2; hw += 8) {
        int y = hw / W2c, xx = hw % W2c;
#pragma unroll
        for (int k = 0; k < 9; k++) {
            int ky = k / 3, kx = k % 3;
            float dy = g_off2[((size_t)b * 18 + 2 * k)     * HW2 + hw];
            float dx = g_off2[((size_t)b * 18 + 2 * k + 1) * HW2 + hw];
            float py = dy + (float)(y - 1 + ky);
            float px = dx + (float)(xx - 1 + kx);
            const float* im = &sh[lane * 197];
            float v = bilin(im, H2, W2c, py, px);
            g_samp[((size_t)(b * HW2 + hw)) * K2D + k * 32 + lane] = v;
        }
    }
}

// ---------------- GEMM: BM=128 BN=64 BK=16, 256 thr, 8x4 tile, double-buffered ----------------
// MODE 0: g_samp(200704x288) x g_w2r^T(64) -> +bias,relu -> g_h2 m-major [m][64]
// MODE 1: g_h2(1024x12544) x g_fw1r^T(128) split-K partials -> g_a1p
template <int MODE>
__global__ void __launch_bounds__(256) k_gemm(const float* __restrict__ bias,
                                              int lda, int k_chunk, int k_iters) {
    const float* __restrict__ A  = (MODE == 0) ? g_samp : g_h2;
    const float* __restrict__ Bw = (MODE == 0) ? g_w2r  : g_fw1r;
    __shared__ __align__(16) float As[2][16][132];
    __shared__ __align__(16) float Bs[2][16][68];
    int m0 = blockIdx.x * 128, n0 = blockIdx.y * 64;
    int kbase = blockIdx.z * k_chunk;
    int tid = threadIdx.x;
    int ty = tid >> 4, tx = tid & 15;
    int am = tid >> 2, aq = tid & 3;
    const float* Ap0 = &A[(size_t)(m0 + am)      * lda + kbase + aq * 4];
    const float* Ap1 = &A[(size_t)(m0 + am + 64) * lda + kbase + aq * 4];
    const float* Bp  = &Bw[(size_t)(n0 + am)     * lda + kbase + aq * 4];
    float acc[8][4];
#pragma unroll
    for (int i = 0; i < 8; i++)
#pragma unroll
        for (int j = 0; j < 4; j++) acc[i][j] = 0.f;

    float4 va0 = *(const float4*)Ap0;
    float4 va1 = *(const float4*)Ap1;
    float4 vb  = *(const float4*)Bp;
#pragma unroll 1
    for (int t = 0; t < k_iters; t++) {
        int cur = t & 1;
        As[cur][aq * 4 + 0][am] = va0.x; As[cur][aq * 4 + 1][am] = va0.y;
        As[cur][aq * 4 + 2][am] = va0.z; As[cur][aq * 4 + 3][am] = va0.w;
        As[cur][aq * 4 + 0][am + 64] = va1.x; As[cur][aq * 4 + 1][am + 64] = va1.y;
        As[cur][aq * 4 + 2][am + 64] = va1.z; As[cur][aq * 4 + 3][am + 64] = va1.w;
        Bs[cur][aq * 4 + 0][am] = vb.x; Bs[cur][aq * 4 + 1][am] = vb.y;
        Bs[cur][aq * 4 + 2][am] = vb.z; Bs[cur][aq * 4 + 3][am] = vb.w;
        __syncthreads();
        if (t + 1 < k_iters) {
            va0 = *(const float4*)(Ap0 + (t + 1) * 16);
            va1 = *(const float4*)(Ap1 + (t + 1) * 16);
            vb  = *(const float4*)(Bp  + (t + 1) * 16);
        }
#pragma unroll
        for (int k = 0; k < 16; k++) {
            float4 a0 = *(const float4*)&As[cur][k][ty * 8];
            float4 a1 = *(const float4*)&As[cur][k][ty * 8 + 4];
            float4 b0 = *(const float4*)&Bs[cur][k][tx * 4];
            float ar[8] = {a0.x, a0.y, a0.z, a0.w, a1.x, a1.y, a1.z, a1.w};
            float br[4] = {b0.x, b0.y, b0.z, b0.w};
#pragma unroll
            for (int i = 0; i < 8; i++)
#pragma unroll
                for (int j = 0; j < 4; j++) acc[i][j] += ar[i] * br[j];
        }
        if (t + 1 < k_iters) __syncthreads();
    }

    float4 bv = make_float4(0.f, 0.f, 0.f, 0.f);
    if (MODE == 0) bv = *(const float4*)&bias[n0 + tx * 4];
#pragma unroll
    for (int i = 0; i < 8; i++) {
        int m = m0 + ty * 8 + i;
        float4 v = make_float4(acc[i][0], acc[i][1], acc[i][2], acc[i][3]);
        if (MODE == 0) {
            v.x = fmaxf(v.x + bv.x, 0.f); v.y = fmaxf(v.y + bv.y, 0.f);
            v.z = fmaxf(v.z + bv.z, 0.f); v.w = fmaxf(v.w + bv.w, 0.f);
            *(float4*)&g_h2[(size_t)m * C2 + n0 + tx * 4] = v;
        } else {
            *(float4*)&g_a1p[((size_t)blockIdx.z * NB + m) * FCN + n0 + tx * 4] = v;
        }
    }
}

// ---------------- reduce split-K + bias + relu ----------------
__global__ void __launch_bounds__(256) k_fc1fin(const float* __restrict__ fb1) {
    int t = blockIdx.x * blockDim.x + threadIdx.x;
    if (t >= NB * FCN) return;
    int n = t & (FCN - 1);
    float s = fb1[n];
#pragma unroll
    for (int z = 0; z < SPLITK; z++) s += g_a1p[(size_t)z * NB * FCN + t];
    g_a1[t] = fmaxf(s, 0.f);
}

// ---------------- fc2 ----------------
__global__ void __launch_bounds__(256) k_fc2(const float* __restrict__ fw2,
                                             const float* __restrict__ fb2,
                                             float* __restrict__ out) {
    int t = blockIdx.x * blockDim.x + threadIdx.x;
    if (t >= NB * 10) return;
    int b = t / 10, o = t % 10;
    float s = fb2[o];
    const float* a = &g_a1[(size_t)b * FCN];
    const float* w = &fw2[(size_t)o * FCN];
#pragma unroll 16
    for (int j = 0; j < FCN; j++) s += a[j] * w[j];
    out[t] = s;
}

// ---------------- launch ----------------
extern "C" void kernel_launch(void* const* d_in, const int* in_sizes, int n_in,
                              void* d_out, int out_size) {
    const float* x   = (const float*)d_in[0];
    const float* ow1 = (const float*)d_in[1];
    const float* ob1 = (const float*)d_in[2];
    const float* w1  = (const float*)d_in[3];
    const float* b1  = (const float*)d_in[4];
    const float* ow2 = (const float*)d_in[5];
    const float* ob2 = (const float*)d_in[6];
    const float* w2  = (const float*)d_in[7];
    const float* b2  = (const float*)d_in[8];
    const float* fw1 = (const float*)d_in[9];
    const float* fb1 = (const float*)d_in[10];
    const float* fw2 = (const float*)d_in[11];
    const float* fb2 = (const float*)d_in[12];
    float* out = (float*)d_out;
    (void)in_sizes; (void)n_in; (void)out_size;

    k_prep<<<784, 256>>>(w2, fw1);
    k_deform1<<<NB, 224>>>(x, ow1, ob1, w1, b1);
    k_offset2<<<NB, 192>>>(ow2, ob2);
    k_samp<<<NB, 256>>>();
    k_gemm<0><<<dim3(1568, 1, 1), 256>>>(b2, K2D, 0, 18);
    k_gemm<1><<<dim3(8, 2, SPLITK), 256>>>(nullptr, FCK, KCHUNK, KCHUNK / 16);
    k_fc1fin<<<(NB * FCN) / 256, 256>>>(fb1);
    k_fc2<<<(NB * 10 + 255) / 256, 256>>>(fw2, fb2, out);
}

// round 4
// speedup vs baseline: 1.1567x; 1.0638x over previous
#include <cuda_runtime.h>
#include <cstdint>

// ---------------- problem constants ----------------
#define NB   1024
#define H1   28
#define W1   28
#define HW1  784
#define H2   14
#define W2c  14
#define HW2  196
#define C1   32
#define C2   64
#define K2D  288      // 32*9
#define FCK  12544    // 64*196
#define FCN  128
#define SPLITK 16
#define KCHUNK 784

// ---------------- f32x2 packed math ----------------
#define PK2(d, x, y)  asm("mov.b64 %0, {%1,%2};" : "=l"(d) : "f"(x), "f"(y))
#define UPK2(x, y, d) asm("mov.b64 {%0,%1}, %2;" : "=f"(x), "=f"(y) : "l"(d))
#define FMA2(c, a, b) asm("fma.rn.f32x2 %0, %1, %2, %0;" : "+l"(c) : "l"(a), "l"(b))

// ---------------- device scratch ----------------
__device__ float g_h1  [(size_t)NB * C1 * HW2];
__device__ float g_off2[(size_t)NB * 18 * HW2];
__device__ float g_w2r [C2 * K2D];                       // [o][kt*32+c]
__device__ float g_fw1r[(size_t)FCN * FCK];              // [n][hw*64+c]
__device__ float g_samp[(size_t)NB * HW2 * K2D];         // [(b*196+hw)][kt*32+c]
__device__ float g_h2  [(size_t)NB * HW2 * C2];          // [(b*196+hw)][c]  (m-major)
__device__ float g_a1p [(size_t)SPLITK * NB * FCN];
__device__ float g_a1  [(size_t)NB * FCN];

// ---------------- helpers ----------------
__device__ __forceinline__ float bilin(const float* __restrict__ img, int H, int W,
                                       float py, float px) {
    float y0f = floorf(py), x0f = floorf(px);
    int y0 = (int)y0f, x0 = (int)x0f;
    float wy1 = py - y0f, wx1 = px - x0f;
    float wy0 = 1.f - wy1, wx0 = 1.f - wx1;
    bool yv0 = (y0 >= 0) && (y0 < H);
    bool yv1 = (y0 >= -1) && (y0 < H - 1);
    bool xv0 = (x0 >= 0) && (x0 < W);
    bool xv1 = (x0 >= -1) && (x0 < W - 1);
    int yc0 = min(max(y0, 0), H - 1),   yc1 = min(max(y0 + 1, 0), H - 1);
    int xc0 = min(max(x0, 0), W - 1),   xc1 = min(max(x0 + 1, 0), W - 1);
    float v = 0.f;
    v += (yv0 && xv0) ? wy0 * wx0 * img[yc0 * W + xc0] : 0.f;
    v += (yv0 && xv1) ? wy0 * wx1 * img[yc0 * W + xc1] : 0.f;
    v += (yv1 && xv0) ? wy1 * wx0 * img[yc1 * W + xc0] : 0.f;
    v += (yv1 && xv1) ? wy1 * wx1 * img[yc1 * W + xc1] : 0.f;
    return v;
}

// ---------------- K0: weight rearranges ----------------
__global__ void k_prep(const float* __restrict__ w2, const float* __restrict__ fw1) {
    int t = blockIdx.x * blockDim.x + threadIdx.x;
    if (t < C2 * K2D) {
        int o = t / K2D, r = t % K2D, kt = r / 32, c = r % 32;
        g_w2r[t] = w2[o * K2D + c * 9 + kt];
    }
    int stride = gridDim.x * blockDim.x;
    for (int i = t; i < FCN * FCK; i += stride) {
        int n = i / FCK, r = i % FCK, hw = r / 64, c = r % 64;
        g_fw1r[i] = fw1[(size_t)n * FCK + c * HW2 + hw];
    }
}

// ---------------- K1: fused offset-conv1 + deform-conv1 + relu + pool ----------------
__global__ void __launch_bounds__(224) k_deform1(const float* __restrict__ x,
                                                 const float* __restrict__ ow1,
                                                 const float* __restrict__ ob1,
                                                 const float* __restrict__ w1,
                                                 const float* __restrict__ b1) {
    int b = blockIdx.x;
    __shared__ float sx[HW1];
    __shared__ float sow[162];
    __shared__ float sob[18];
    __shared__ float swt[C1 * 9];
    __shared__ float sb[C1];
    for (int i = threadIdx.x; i < HW1; i += 224) sx[i] = x[(size_t)b * HW1 + i];
    if (threadIdx.x < 162) sow[threadIdx.x] = ow1[threadIdx.x];
    if (threadIdx.x < 18)  sob[threadIdx.x] = ob1[threadIdx.x];
    for (int i = threadIdx.x; i < C1 * 9; i += 224) swt[i] = w1[i];
    if (threadIdx.x < C1) sb[threadIdx.x] = b1[threadIdx.x];
    __syncthreads();
    int t = threadIdx.x;
    if (t >= HW2) return;
    int ph = t / W2c, pw = t % W2c;
    float acc[C1];
#pragma unroll
    for (int o = 0; o < C1; o++) acc[o] = 0.f;
#pragma unroll 1
    for (int s4 = 0; s4 < 4; s4++) {
        int y = ph * 2 + (s4 >> 1), w = pw * 2 + (s4 & 1);
        float p[9];
#pragma unroll
        for (int ky = 0; ky < 3; ky++)
#pragma unroll
            for (int kx = 0; kx < 3; kx++) {
                int y2 = y + ky - 1, x2 = w + kx - 1;
                bool ok = (y2 >= 0) && (y2 < H1) && (x2 >= 0) && (x2 < W1);
                p[ky * 3 + kx] = ok ? sx[y2 * W1 + x2] : 0.f;
            }
        float s[9];
#pragma unroll
        for (int k = 0; k < 9; k++) {
            float dy = sob[2 * k], dx = sob[2 * k + 1];
#pragma unroll
            for (int j = 0; j < 9; j++) {
                dy += sow[(2 * k) * 9 + j] * p[j];
                dx += sow[(2 * k + 1) * 9 + j] * p[j];
            }
            int ky = k / 3, kx = k % 3;
            s[k] = bilin(sx, H1, W1, dy + (float)(y - 1 + ky), dx + (float)(w - 1 + kx));
        }
#pragma unroll
        for (int o = 0; o < C1; o++) {
            float v = sb[o];
#pragma unroll
            for (int k = 0; k < 9; k++) v += swt[o * 9 + k] * s[k];
            acc[o] += fmaxf(v, 0.f);
        }
    }
#pragma unroll
    for (int o = 0; o < C1; o++)
        g_h1[((size_t)b * C1 + o) * HW2 + t] = acc[o] * 0.25f;
}

// ---------------- K2: offset conv2, padded smem + register neighborhood ----------------
__global__ void __launch_bounds__(192) k_offset2(const float* __restrict__ ow2,
                                                 const float* __restrict__ ob2) {
    int b = blockIdx.x;
    __shared__ float sh[16 * 256];
    __shared__ float sw[18 * 144];
    int t = threadIdx.x;
    bool act = t < 168;
    int og = t / 28, pg = t % 28;
    int y = pg >> 1, x0 = (pg & 1) * 7;
    int o0 = og * 3;
    float acc[3][7];
    if (act) {
#pragma unroll
        for (int q = 0; q < 3; q++) {
            float bv = ob2[o0 + q];
#pragma unroll
            for (int p = 0; p < 7; p++) acc[q][p] = bv;
        }
    }
#pragma unroll 1
    for (int half = 0; half < 2; half++) {
        if (half) __syncthreads();
        for (int i = t; i < 16 * 60; i += 192) {
            int c = i / 60, e = i % 60;
            int py, px;
            if (e < 16)      { py = 0;  px = e; }
            else if (e < 32) { py = 15; px = e - 16; }
            else { int e2 = e - 32; py = 1 + (e2 >> 1); px = (e2 & 1) * 15; }
            sh[c * 256 + py * 16 + px] = 0.f;
        }
        for (int i = t; i < 16 * HW2; i += 192) {
            int c = i / HW2, hw = i % HW2, yy = hw / W2c, xx = hw % W2c;
            sh[c * 256 + (yy + 1) * 16 + (xx + 1)] =
                g_h1[(size_t)b * (C1 * HW2) + (half * 16 + c) * HW2 + hw];
        }
        for (int i = t; i < 18 * 144; i += 192) {
            int o = i / 144, r = i % 144, cl = r / 9, kt = r % 9;
            sw[i] = ow2[o * K2D + (half * 16 + cl) * 9 + kt];
        }
        __syncthreads();
        if (act) {
#pragma unroll 1
            for (int c = 0; c < 16; c++) {
                const float* base = &sh[c * 256 + y * 16 + x0];
                float nb[27];
#pragma unroll
                for (int dy = 0; dy < 3; dy++)
#pragma unroll
                    for (int dx = 0; dx < 9; dx++)
                        nb[dy * 9 + dx] = base[dy * 16 + dx];
#pragma unroll
                for (int kt = 0; kt < 9; kt++) {
                    int ky = kt / 3, kx = kt % 3;
                    float w0 = sw[(o0 + 0) * 144 + c * 9 + kt];
                    float w1v = sw[(o0 + 1) * 144 + c * 9 + kt];
                    float w2v = sw[(o0 + 2) * 144 + c * 9 + kt];
#pragma unroll
                    for (int p = 0; p < 7; p++) {
                        float v = nb[ky * 9 + kx + p];
                        acc[0][p] += w0 * v;
                        acc[1][p] += w1v * v;
                        acc[2][p] += w2v * v;
                    }
                }
            }
        }
    }
    if (act) {
#pragma unroll
        for (int q = 0; q < 3; q++)
#pragma unroll
            for (int p = 0; p < 7; p++)
                g_off2[((size_t)b * 18 + o0 + q) * HW2 + y * W2c + x0 + p] = acc[q][p];
    }
}

// ---------------- K3: bilinear sampling -> im2col (shfl-broadcast params) ----------------
__global__ void __launch_bounds__(256) k_samp() {
    int b = blockIdx.x;
    __shared__ float sh[C1 * 197];
    for (int i = threadIdx.x; i < C1 * HW2; i += blockDim.x) {
        int c = i / HW2, hw = i % HW2;
        sh[c * 197 + hw] = g_h1[(size_t)b * (C1 * HW2) + i];
    }
    __syncthreads();
    int warp = threadIdx.x >> 5, lane = threadIdx.x & 31;
    const float* im = &sh[lane * 197];
#pragma unroll 1
    for (int hw = warp; hw < HW2; hw += 8) {
        int y = hw / W2c, xx = hw % W2c;
        // lanes 0..8 compute bilinear params for their tap
        float w00 = 0.f, w01 = 0.f, w10 = 0.f, w11 = 0.f;
        int i00 = 0, i01 = 0, i10 = 0, i11 = 0;
        if (lane < 9) {
            int k = lane, ky = k / 3, kx = k % 3;
            float dy = g_off2[((size_t)b * 18 + 2 * k)     * HW2 + hw];
            float dx = g_off2[((size_t)b * 18 + 2 * k + 1) * HW2 + hw];
            float py = dy + (float)(y - 1 + ky);
            float px = dx + (float)(xx - 1 + kx);
            float y0f = floorf(py), x0f = floorf(px);
            int y0 = (int)y0f, x0 = (int)x0f;
            float wy1 = py - y0f, wx1 = px - x0f;
            float wy0 = 1.f - wy1, wx0 = 1.f - wx1;
            bool yv0 = (y0 >= 0) && (y0 < H2), yv1 = (y0 >= -1) && (y0 < H2 - 1);
            bool xv0 = (x0 >= 0) && (x0 < W2c), xv1 = (x0 >= -1) && (x0 < W2c - 1);
            int yc0 = min(max(y0, 0), H2 - 1),  yc1 = min(max(y0 + 1, 0), H2 - 1);
            int xc0 = min(max(x0, 0), W2c - 1), xc1 = min(max(x0 + 1, 0), W2c - 1);
            w00 = (yv0 && xv0) ? wy0 * wx0 : 0.f;
            w01 = (yv0 && xv1) ? wy0 * wx1 : 0.f;
            w10 = (yv1 && xv0) ? wy1 * wx0 : 0.f;
            w11 = (yv1 && xv1) ? wy1 * wx1 : 0.f;
            i00 = yc0 * W2c + xc0; i01 = yc0 * W2c + xc1;
            i10 = yc1 * W2c + xc0; i11 = yc1 * W2c + xc1;
        }
        size_t outbase = ((size_t)(b * HW2 + hw)) * K2D + lane;
#pragma unroll
        for (int k = 0; k < 9; k++) {
            float u00 = __shfl_sync(0xffffffffu, w00, k);
            float u01 = __shfl_sync(0xffffffffu, w01, k);
            float u10 = __shfl_sync(0xffffffffu, w10, k);
            float u11 = __shfl_sync(0xffffffffu, w11, k);
            int   j00 = __shfl_sync(0xffffffffu, i00, k);
            int   j01 = __shfl_sync(0xffffffffu, i01, k);
            int   j10 = __shfl_sync(0xffffffffu, i10, k);
            int   j11 = __shfl_sync(0xffffffffu, i11, k);
            float v = u00 * im[j00] + u01 * im[j01] + u10 * im[j10] + u11 * im[j11];
            g_samp[outbase + k * 32] = v;
        }
    }
}

// ---------------- GEMM: BM=128 BN=64 BK=16, 256 thr, 8x4 tile, f32x2 FMA ----------------
// MODE 0: g_samp(200704x288) x g_w2r^T(64) -> +bias,relu -> g_h2 m-major [m][64]
// MODE 1: g_h2(1024x12544) x g_fw1r^T(128) split-K partials -> g_a1p
template <int MODE>
__global__ void __launch_bounds__(256) k_gemm(const float* __restrict__ bias,
                                              int lda, int k_chunk, int k_iters) {
    const float* __restrict__ A  = (MODE == 0) ? g_samp : g_h2;
    const float* __restrict__ Bw = (MODE == 0) ? g_w2r  : g_fw1r;
    __shared__ __align__(16) float As[2][16][132];
    __shared__ __align__(16) float Bs[2][16][68];
    int m0 = blockIdx.x * 128, n0 = blockIdx.y * 64;
    int kbase = blockIdx.z * k_chunk;
    int tid = threadIdx.x;
    int ty = tid >> 4, tx = tid & 15;
    int am = tid >> 2, aq = tid & 3;
    const float* Ap0 = &A[(size_t)(m0 + am)      * lda + kbase + aq * 4];
    const float* Ap1 = &A[(size_t)(m0 + am + 64) * lda + kbase + aq * 4];
    const float* Bp  = &Bw[(size_t)(n0 + am)     * lda + kbase + aq * 4];
    // acc pairs over adjacent m: accp[p][j] = (acc[2p][j], acc[2p+1][j])
    unsigned long long accp[4][4];
#pragma unroll
    for (int i = 0; i < 4; i++)
#pragma unroll
        for (int j = 0; j < 4; j++) accp[i][j] = 0ull;

    float4 va0 = *(const float4*)Ap0;
    float4 va1 = *(const float4*)Ap1;
    float4 vb  = *(const float4*)Bp;
#pragma unroll 1
    for (int t = 0; t < k_iters; t++) {
        int cur = t & 1;
        As[cur][aq * 4 + 0][am] = va0.x; As[cur][aq * 4 + 1][am] = va0.y;
        As[cur][aq * 4 + 2][am] = va0.z; As[cur][aq * 4 + 3][am] = va0.w;
        As[cur][aq * 4 + 0][am + 64] = va1.x; As[cur][aq * 4 + 1][am + 64] = va1.y;
        As[cur][aq * 4 + 2][am + 64] = va1.z; As[cur][aq * 4 + 3][am + 64] = va1.w;
        Bs[cur][aq * 4 + 0][am] = vb.x; Bs[cur][aq * 4 + 1][am] = vb.y;
        Bs[cur][aq * 4 + 2][am] = vb.z; Bs[cur][aq * 4 + 3][am] = vb.w;
        __syncthreads();
        if (t + 1 < k_iters) {
            va0 = *(const float4*)(Ap0 + (t + 1) * 16);
            va1 = *(const float4*)(Ap1 + (t + 1) * 16);
            vb  = *(const float4*)(Bp  + (t + 1) * 16);
        }
#pragma unroll
        for (int k = 0; k < 16; k++) {
            float4 a0 = *(const float4*)&As[cur][k][ty * 8];
            float4 a1 = *(const float4*)&As[cur][k][ty * 8 + 4];
            float4 b0 = *(const float4*)&Bs[cur][k][tx * 4];
            unsigned long long ap[4], bp[4];
            PK2(ap[0], a0.x, a0.y); PK2(ap[1], a0.z, a0.w);
            PK2(ap[2], a1.x, a1.y); PK2(ap[3], a1.z, a1.w);
            PK2(bp[0], b0.x, b0.x); PK2(bp[1], b0.y, b0.y);
            PK2(bp[2], b0.z, b0.z); PK2(bp[3], b0.w, b0.w);
#pragma unroll
            for (int i = 0; i < 4; i++)
#pragma unroll
                for (int j = 0; j < 4; j++) FMA2(accp[i][j], ap[i], bp[j]);
        }
        if (t + 1 < k_iters) __syncthreads();
    }

    // unpack pairs -> rows
    float r[8][4];
#pragma unroll
    for (int p = 0; p < 4; p++)
#pragma unroll
        for (int j = 0; j < 4; j++) {
            float lo, hi;
            UPK2(lo, hi, accp[p][j]);
            r[2 * p][j] = lo; r[2 * p + 1][j] = hi;
        }

    float4 bv = make_float4(0.f, 0.f, 0.f, 0.f);
    if (MODE == 0) bv = *(const float4*)&bias[n0 + tx * 4];
#pragma unroll
    for (int i = 0; i < 8; i++) {
        int m = m0 + ty * 8 + i;
        float4 v = make_float4(r[i][0], r[i][1], r[i][2], r[i][3]);
        if (MODE == 0) {
            v.x = fmaxf(v.x + bv.x, 0.f); v.y = fmaxf(v.y + bv.y, 0.f);
            v.z = fmaxf(v.z + bv.z, 0.f); v.w = fmaxf(v.w + bv.w, 0.f);
            *(float4*)&g_h2[(size_t)m * C2 + n0 + tx * 4] = v;
        } else {
            *(float4*)&g_a1p[((size_t)blockIdx.z * NB + m) * FCN + n0 + tx * 4] = v;
        }
    }
}

// ---------------- reduce split-K + bias + relu ----------------
__global__ void __launch_bounds__(256) k_fc1fin(const float* __restrict__ fb1) {
    int t = blockIdx.x * blockDim.x + threadIdx.x;
    if (t >= NB * FCN) return;
    int n = t & (FCN - 1);
    float s = fb1[n];
#pragma unroll
    for (int z = 0; z < SPLITK; z++) s += g_a1p[(size_t)z * NB * FCN + t];
    g_a1[t] = fmaxf(s, 0.f);
}

// ---------------- fc2 ----------------
__global__ void __launch_bounds__(256) k_fc2(const float* __restrict__ fw2,
                                             const float* __restrict__ fb2,
                                             float* __restrict__ out) {
    int t = blockIdx.x * blockDim.x + threadIdx.x;
    if (t >= NB * 10) return;
    int b = t / 10, o = t % 10;
    float s = fb2[o];
    const float* a = &g_a1[(size_t)b * FCN];
    const float* w = &fw2[(size_t)o * FCN];
#pragma unroll 16
    for (int j = 0; j < FCN; j++) s += a[j] * w[j];
    out[t] = s;
}

// ---------------- launch ----------------
extern "C" void kernel_launch(void* const* d_in, const int* in_sizes, int n_in,
                              void* d_out, int out_size) {
    const float* x   = (const float*)d_in[0];
    const float* ow1 = (const float*)d_in[1];
    const float* ob1 = (const float*)d_in[2];
    const float* w1  = (const float*)d_in[3];
    const float* b1  = (const float*)d_in[4];
    const float* ow2 = (const float*)d_in[5];
    const float* ob2 = (const float*)d_in[6];
    const float* w2  = (const float*)d_in[7];
    const float* b2  = (const float*)d_in[8];
    const float* fw1 = (const float*)d_in[9];
    const float* fb1 = (const float*)d_in[10];
    const float* fw2 = (const float*)d_in[11];
    const float* fb2 = (const float*)d_in[12];
    float* out = (float*)d_out;
    (void)in_sizes; (void)n_in; (void)out_size;

    k_prep<<<784, 256>>>(w2, fw1);
    k_deform1<<<NB, 224>>>(x, ow1, ob1, w1, b1);
    k_offset2<<<NB, 192>>>(ow2, ob2);
    k_samp<<<NB, 256>>>();
    k_gemm<0><<<dim3(1568, 1, 1), 256>>>(b2, K2D, 0, 18);
    k_gemm<1><<<dim3(8, 2, SPLITK), 256>>>(nullptr, FCK, KCHUNK, KCHUNK / 16);
    k_fc1fin<<<(NB * FCN) / 256, 256>>>(fb1);
    k_fc2<<<(NB * 10 + 255) / 256, 256>>>(fw2, fb2, out);
}